// round 2
// baseline (speedup 1.0000x reference)
#include <cuda_runtime.h>
#include <cuda_bf16.h>
#include <cstdint>

// ---------------- problem constants ----------------
#define N_ROI    116
#define HIDDEN   64
#define N_NODES  118784           // 1024 * 116
#define N_GRAPHS 1024
#define D1       3712             // 116*32
#define DIN1     7424             // 116*64
#define CH4      29               // 116 floats = 29 float4

// ---------------- scratch (no allocations allowed) ----------------
__device__ float4 g_agg[(size_t)N_NODES * CH4];        // 55.1 MB (sum aggregate, reused)
__device__ float  g_deg[N_NODES];                      // degree
__device__ float4 g_h1[(size_t)N_NODES * CH4];         // 55.1 MB layer-1 output [N,116]
__device__ float4 g_h2[(size_t)N_NODES * (HIDDEN/4)];  // 30.4 MB layer-2 output [N,64] == [1024,7424]
__device__ float  g_lin1[(size_t)N_GRAPHS * D1];       // 15.2 MB lin1 output

// ---------------- helpers ----------------
__device__ __forceinline__ float mish_f(float x) {
    float sp = (x > 20.0f) ? x : log1pf(__expf(x));
    return x * tanhf(sp);
}

// ---------------- zero kernels ----------------
__global__ void zero_agg_deg() {
    size_t i = (size_t)blockIdx.x * blockDim.x + threadIdx.x;
    size_t stride = (size_t)gridDim.x * blockDim.x;
    const size_t n4 = (size_t)N_NODES * CH4;
    float4 z = make_float4(0.f, 0.f, 0.f, 0.f);
    for (size_t k = i; k < n4; k += stride) g_agg[k] = z;
    for (size_t k = i; k < N_NODES; k += stride) g_deg[k] = 0.f;
}
__global__ void zero_agg() {
    size_t i = (size_t)blockIdx.x * blockDim.x + threadIdx.x;
    size_t stride = (size_t)gridDim.x * blockDim.x;
    const size_t n4 = (size_t)N_NODES * CH4;
    float4 z = make_float4(0.f, 0.f, 0.f, 0.f);
    for (size_t k = i; k < n4; k += stride) g_agg[k] = z;
}

// ---------------- scatter-add (warp per edge, vector red) ----------------
// edge_index arrives as int32 (harness downcasts int64 -> int32), layout [2, E].
template<bool DODEG>
__global__ void scatter_kernel(const float4* __restrict__ feat,
                               const int* __restrict__ ei, int E) {
    long long gw = ((long long)blockIdx.x * blockDim.x + threadIdx.x) >> 5;
    int lane = threadIdx.x & 31;
    if (gw >= E) return;
    int s = ei[gw];
    int d = ei[(long long)E + gw];
    if (lane < CH4) {
        float4 v = feat[(size_t)s * CH4 + lane];
        float4* p = &g_agg[(size_t)d * CH4 + lane];
        asm volatile("red.global.add.v4.f32 [%0], {%1,%2,%3,%4};"
                     :: "l"(p), "f"(v.x), "f"(v.y), "f"(v.z), "f"(v.w) : "memory");
    } else if (DODEG && lane == 29) {
        atomicAdd(&g_deg[d], 1.0f);
    }
}

// ---------------- fused SAGE layer GEMM ----------------
// out[n,j] = mish( mean[n,:]@WL[:,j] + A[n,:]@WR[:,j] + bias[j] ),  mean = g_agg/max(deg,1)
// K = 116 in 4 chunks of 29. Block = (NOUT, NTY), 32 rows per block.
template<int NOUT, int NTY>
__global__ void sage_gemm(const float* __restrict__ A,
                          const float* __restrict__ WL,
                          const float* __restrict__ WR,
                          const float* __restrict__ bias,
                          float* __restrict__ out) {
    const int ROWS = 32, KC = 29, RPT = ROWS / NTY;
    __shared__ float as_[ROWS][KC];
    __shared__ float ms_[ROWS][KC];
    __shared__ float wl_[KC][NOUT];
    __shared__ float wr_[KC][NOUT];
    __shared__ float rdeg[ROWS];

    int tx = threadIdx.x, ty = threadIdx.y;
    int tid = ty * NOUT + tx;
    const int nthr = NOUT * NTY;
    int row0 = blockIdx.x * ROWS;
    const float* AGG = (const float*)g_agg;

    for (int i = tid; i < ROWS; i += nthr) {
        float dgv = g_deg[row0 + i];
        rdeg[i] = 1.0f / fmaxf(dgv, 1.0f);
    }

    float acc[RPT];
#pragma unroll
    for (int r = 0; r < RPT; r++) acc[r] = 0.f;

    for (int kc = 0; kc < N_ROI; kc += KC) {
        __syncthreads();
        for (int i = tid; i < ROWS * KC; i += nthr) {
            int r = i / KC, k = i % KC;
            size_t gi = (size_t)(row0 + r) * N_ROI + kc + k;
            as_[r][k] = A[gi];
            ms_[r][k] = AGG[gi] * rdeg[r];
        }
        for (int i = tid; i < KC * NOUT; i += nthr) {
            int k = i / NOUT, j = i % NOUT;
            wl_[k][j] = WL[(size_t)(kc + k) * NOUT + j];
            wr_[k][j] = WR[(size_t)(kc + k) * NOUT + j];
        }
        __syncthreads();
#pragma unroll
        for (int k = 0; k < KC; k++) {
            float wlv = wl_[k][tx];
            float wrv = wr_[k][tx];
#pragma unroll
            for (int r = 0; r < RPT; r++) {
                int rr = r * NTY + ty;
                acc[r] = fmaf(ms_[rr][k], wlv, acc[r]);
                acc[r] = fmaf(as_[rr][k], wrv, acc[r]);
            }
        }
    }
    float bv = bias[tx];
#pragma unroll
    for (int r = 0; r < RPT; r++) {
        int rr = r * NTY + ty;
        out[(size_t)(row0 + rr) * NOUT + tx] = mish_f(acc[r] + bv);
    }
}

// ---------------- big dense GEMM: C[M,N] = A[M,K] @ B[K,N] + bias ----------------
// M=1024, N=3712, K=7424 all multiples of tile dims; no bounds checks.
__global__ void __launch_bounds__(256, 2)
sgemm128(const float* __restrict__ A, const float* __restrict__ B,
         const float* __restrict__ bias, float* __restrict__ C,
         int M, int N, int K) {
    __shared__ float As[8][128];
    __shared__ float Bs[8][128];
    int tid = threadIdx.x;
    int brow = blockIdx.y * 128;
    int bcol = blockIdx.x * 128;

    int a_r = tid >> 1;            // 0..127
    int a_k = (tid & 1) * 4;       // 0 or 4
    int b_k = tid >> 5;            // 0..7
    int b_c = (tid & 31) * 4;      // 0..124

    int tr = (tid >> 4) * 8;       // 0..120
    int tc = (tid & 15) * 8;       // 0..120

    float acc[8][8];
#pragma unroll
    for (int i = 0; i < 8; i++)
#pragma unroll
        for (int j = 0; j < 8; j++) acc[i][j] = 0.f;

    for (int k0 = 0; k0 < K; k0 += 8) {
        float4 av = *(const float4*)&A[(size_t)(brow + a_r) * K + k0 + a_k];
        float4 bv = *(const float4*)&B[(size_t)(k0 + b_k) * N + bcol + b_c];
        __syncthreads();
        As[a_k + 0][a_r] = av.x;
        As[a_k + 1][a_r] = av.y;
        As[a_k + 2][a_r] = av.z;
        As[a_k + 3][a_r] = av.w;
        *(float4*)&Bs[b_k][b_c] = bv;
        __syncthreads();
#pragma unroll
        for (int k = 0; k < 8; k++) {
            float ar[8], br[8];
            *(float4*)(ar)     = *(const float4*)&As[k][tr];
            *(float4*)(ar + 4) = *(const float4*)&As[k][tr + 4];
            *(float4*)(br)     = *(const float4*)&Bs[k][tc];
            *(float4*)(br + 4) = *(const float4*)&Bs[k][tc + 4];
#pragma unroll
            for (int i = 0; i < 8; i++)
#pragma unroll
                for (int j = 0; j < 8; j++)
                    acc[i][j] = fmaf(ar[i], br[j], acc[i][j]);
        }
    }
#pragma unroll
    for (int i = 0; i < 8; i++) {
        size_t rowoff = (size_t)(brow + tr + i) * N + bcol + tc;
#pragma unroll
        for (int j4 = 0; j4 < 8; j4 += 4) {
            float4 v;
            v.x = acc[i][j4 + 0] + bias[bcol + tc + j4 + 0];
            v.y = acc[i][j4 + 1] + bias[bcol + tc + j4 + 1];
            v.z = acc[i][j4 + 2] + bias[bcol + tc + j4 + 2];
            v.w = acc[i][j4 + 3] + bias[bcol + tc + j4 + 3];
            *(float4*)&C[rowoff + j4] = v;
        }
    }
}

// ---------------- fused LayerNorm + mish + lin2 ----------------
__device__ __forceinline__ void block_reduce2(float& a, float& b, float* sbuf) {
#pragma unroll
    for (int o = 16; o; o >>= 1) {
        a += __shfl_down_sync(0xffffffffu, a, o);
        b += __shfl_down_sync(0xffffffffu, b, o);
    }
    int w = threadIdx.x >> 5;
    __syncthreads();
    if ((threadIdx.x & 31) == 0) { sbuf[w] = a; sbuf[w + 8] = b; }
    __syncthreads();
    if (threadIdx.x < 32) {
        a = (threadIdx.x < 8) ? sbuf[threadIdx.x] : 0.f;
        b = (threadIdx.x < 8) ? sbuf[threadIdx.x + 8] : 0.f;
#pragma unroll
        for (int o = 4; o; o >>= 1) {
            a += __shfl_down_sync(0xffffffffu, a, o);
            b += __shfl_down_sync(0xffffffffu, b, o);
        }
        if (threadIdx.x == 0) { sbuf[16] = a; sbuf[17] = b; }
    }
    __syncthreads();
    a = sbuf[16];
    b = sbuf[17];
}

__global__ void ln_mish_lin2(const float* __restrict__ H,
                             const float* __restrict__ g,
                             const float* __restrict__ bb,
                             const float* __restrict__ w2,
                             const float* __restrict__ b2,
                             float* __restrict__ out) {
    __shared__ float sbuf[18];
    int row = blockIdx.x;
    const float* h = H + (size_t)row * D1;
    int tid = threadIdx.x;

    float s = 0.f, s2 = 0.f;
    for (int k = tid; k < D1; k += 256) {
        float v = h[k];
        s += v;
        s2 = fmaf(v, v, s2);
    }
    block_reduce2(s, s2, sbuf);
    float mu = s * (1.0f / D1);
    float var = s2 * (1.0f / D1) - mu * mu;
    float rstd = rsqrtf(var + 1e-5f);

    float a0 = 0.f, a1 = 0.f;
    for (int k = tid; k < D1; k += 256) {
        float v = (h[k] - mu) * rstd * g[k] + bb[k];
        v = mish_f(v);
        a0 = fmaf(v, w2[2 * k + 0], a0);
        a1 = fmaf(v, w2[2 * k + 1], a1);
    }
    block_reduce2(a0, a1, sbuf);
    if (tid == 0) {
        out[2 * row + 0] = a0 + b2[0];
        out[2 * row + 1] = a1 + b2[1];
    }
}

// ---------------- launch ----------------
extern "C" void kernel_launch(void* const* d_in, const int* in_sizes, int n_in,
                              void* d_out, int out_size) {
    const float* x      = (const float*)d_in[0];
    const int*   ei     = (const int*)d_in[1];        // int32 (downcast from int64)
    const float* w1_l   = (const float*)d_in[2];
    const float* b1_l   = (const float*)d_in[3];
    const float* w1_r   = (const float*)d_in[4];
    const float* w2_l   = (const float*)d_in[5];
    const float* b2_l   = (const float*)d_in[6];
    const float* w2_r   = (const float*)d_in[7];
    const float* w_lin1 = (const float*)d_in[8];
    const float* b_lin1 = (const float*)d_in[9];
    const float* ln_g   = (const float*)d_in[10];
    const float* ln_b   = (const float*)d_in[11];
    const float* w_lin2 = (const float*)d_in[12];
    const float* b_lin2 = (const float*)d_in[13];
    float* out = (float*)d_out;

    const int E = in_sizes[1] / 2;
    const long long scatter_threads = (long long)E * 32;
    const int scatter_blocks = (int)((scatter_threads + 255) / 256);

    // ---- layer 1 ----
    zero_agg_deg<<<4096, 256>>>();
    scatter_kernel<true><<<scatter_blocks, 256>>>((const float4*)x, ei, E);
    sage_gemm<N_ROI, 2><<<N_NODES / 32, dim3(N_ROI, 2)>>>(
        x, w1_l, w1_r, b1_l, (float*)g_h1);

    // ---- layer 2 ----
    zero_agg<<<4096, 256>>>();
    scatter_kernel<false><<<scatter_blocks, 256>>>((const float4*)g_h1, ei, E);
    sage_gemm<HIDDEN, 4><<<N_NODES / 32, dim3(HIDDEN, 4)>>>(
        (const float*)g_h1, w2_l, w2_r, b2_l, (float*)g_h2);

    // ---- dense head ----
    sgemm128<<<dim3(D1 / 128, N_GRAPHS / 128), 256>>>(
        (const float*)g_h2, w_lin1, b_lin1, g_lin1, N_GRAPHS, D1, DIN1);

    ln_mish_lin2<<<N_GRAPHS, 256>>>(g_lin1, ln_g, ln_b, w_lin2, b_lin2, out);
}

// round 7
// speedup vs baseline: 1.5790x; 1.5790x over previous
#include <cuda_runtime.h>
#include <cuda_bf16.h>
#include <cstdint>

// ---------------- problem constants ----------------
#define N_ROI    116
#define HIDDEN   64
#define N_NODES  118784           // 1024 * 116
#define N_GRAPHS 1024
#define D1       3712             // 116*32
#define KDIM     7424             // 116*64
#define NDIM     3712
#define CH4      29               // 116 floats = 29 float4

using bf16 = __nv_bfloat16;

// ---------------- scratch (no allocations allowed) ----------------
__device__ __align__(256) float4 g_agg[(size_t)N_NODES * CH4];   // 55.1 MB
__device__ __align__(256) float  g_deg[N_NODES];
__device__ __align__(256) float4 g_h1[(size_t)N_NODES * CH4];    // 55.1 MB
__device__ __align__(256) float4 g_h2[(size_t)N_NODES * (HIDDEN/4)]; // 30.4 MB f32
__device__ __align__(256) bf16   g_Ah[(size_t)N_GRAPHS * KDIM];  // 14.8 MB
__device__ __align__(256) bf16   g_Al[(size_t)N_GRAPHS * KDIM];  // 14.8 MB
__device__ __align__(256) bf16   g_Bh[(size_t)NDIM * KDIM];      // 55.1 MB
__device__ __align__(256) bf16   g_Bl[(size_t)NDIM * KDIM];      // 55.1 MB
__device__ __align__(256) float  g_lin1[(size_t)N_GRAPHS * D1];  // 15.2 MB

// ---------------- inline PTX helpers ----------------
__device__ __forceinline__ uint32_t smem_u32(const void* p) {
    uint32_t a;
    asm("{ .reg .u64 t; cvta.to.shared.u64 t, %1; cvt.u32.u64 %0, t; }" : "=r"(a) : "l"(p));
    return a;
}
#define LDSM4(r, addr) \
    asm volatile("ldmatrix.sync.aligned.m8n8.x4.shared.b16 {%0,%1,%2,%3}, [%4];" \
        : "=r"((r)[0]), "=r"((r)[1]), "=r"((r)[2]), "=r"((r)[3]) : "r"(addr))
#define MMA_BF16(d, a, b0, b1) \
    asm volatile("mma.sync.aligned.m16n8k16.row.col.f32.bf16.bf16.f32 " \
        "{%0,%1,%2,%3}, {%4,%5,%6,%7}, {%8,%9}, {%0,%1,%2,%3};" \
        : "+f"((d)[0]), "+f"((d)[1]), "+f"((d)[2]), "+f"((d)[3]) \
        : "r"((a)[0]), "r"((a)[1]), "r"((a)[2]), "r"((a)[3]), "r"(b0), "r"(b1))

// ---------------- helpers ----------------
__device__ __forceinline__ float mish_f(float x) {
    float sp = (x > 20.0f) ? x : log1pf(__expf(x));
    return x * tanhf(sp);
}

// ---------------- zero kernels (R2-proven) ----------------
__global__ void zero_agg_deg() {
    size_t i = (size_t)blockIdx.x * blockDim.x + threadIdx.x;
    size_t stride = (size_t)gridDim.x * blockDim.x;
    const size_t n4 = (size_t)N_NODES * CH4;
    float4 z = make_float4(0.f, 0.f, 0.f, 0.f);
    for (size_t k = i; k < n4; k += stride) g_agg[k] = z;
    for (size_t k = i; k < N_NODES; k += stride) g_deg[k] = 0.f;
}
__global__ void zero_agg() {
    size_t i = (size_t)blockIdx.x * blockDim.x + threadIdx.x;
    size_t stride = (size_t)gridDim.x * blockDim.x;
    const size_t n4 = (size_t)N_NODES * CH4;
    float4 z = make_float4(0.f, 0.f, 0.f, 0.f);
    for (size_t k = i; k < n4; k += stride) g_agg[k] = z;
}

// ---------------- scatter-add (warp per edge, vector red) ----------------
template<bool DODEG>
__global__ void scatter_kernel(const float4* __restrict__ feat,
                               const int* __restrict__ ei, int E) {
    long long gw = ((long long)blockIdx.x * blockDim.x + threadIdx.x) >> 5;
    int lane = threadIdx.x & 31;
    if (gw >= E) return;
    int s = ei[gw];
    int d = ei[(long long)E + gw];
    if (lane < CH4) {
        float4 v = feat[(size_t)s * CH4 + lane];
        float4* p = &g_agg[(size_t)d * CH4 + lane];
        asm volatile("red.global.add.v4.f32 [%0], {%1,%2,%3,%4};"
                     :: "l"(p), "f"(v.x), "f"(v.y), "f"(v.z), "f"(v.w) : "memory");
    } else if (DODEG && lane == 29) {
        atomicAdd(&g_deg[d], 1.0f);
    }
}

// ---------------- fused SAGE layer GEMM (exactly R2's proven version) ------
template<int NOUT, int NTY>
__global__ void sage_gemm(const float* __restrict__ A,
                          const float* __restrict__ WL,
                          const float* __restrict__ WR,
                          const float* __restrict__ bias,
                          float* __restrict__ out) {
    const int ROWS = 32, KC = 29, RPT = ROWS / NTY;
    __shared__ float as_[ROWS][KC];
    __shared__ float ms_[ROWS][KC];
    __shared__ float wl_[KC][NOUT];
    __shared__ float wr_[KC][NOUT];
    __shared__ float rdeg[ROWS];

    int tx = threadIdx.x, ty = threadIdx.y;
    int tid = ty * NOUT + tx;
    const int nthr = NOUT * NTY;
    int row0 = blockIdx.x * ROWS;
    const float* AGG = (const float*)g_agg;

    for (int i = tid; i < ROWS; i += nthr)
        rdeg[i] = 1.0f / fmaxf(g_deg[row0 + i], 1.0f);

    float acc[RPT];
#pragma unroll
    for (int r = 0; r < RPT; r++) acc[r] = 0.f;

    for (int kc = 0; kc < N_ROI; kc += KC) {
        __syncthreads();
        for (int i = tid; i < ROWS * KC; i += nthr) {
            int r = i / KC, k = i % KC;
            size_t gi = (size_t)(row0 + r) * N_ROI + kc + k;
            as_[r][k] = A[gi];
            ms_[r][k] = AGG[gi] * rdeg[r];
        }
        for (int i = tid; i < KC * NOUT; i += nthr) {
            int k = i / NOUT, j = i % NOUT;
            wl_[k][j] = WL[(size_t)(kc + k) * NOUT + j];
            wr_[k][j] = WR[(size_t)(kc + k) * NOUT + j];
        }
        __syncthreads();
#pragma unroll
        for (int k = 0; k < KC; k++) {
            float wlv = wl_[k][tx];
            float wrv = wr_[k][tx];
#pragma unroll
            for (int r = 0; r < RPT; r++) {
                int rr = r * NTY + ty;
                acc[r] = fmaf(ms_[rr][k], wlv, acc[r]);
                acc[r] = fmaf(as_[rr][k], wrv, acc[r]);
            }
        }
    }
    float bv = bias[tx];
#pragma unroll
    for (int r = 0; r < RPT; r++) {
        int rr = r * NTY + ty;
        out[(size_t)(row0 + rr) * NOUT + tx] = mish_f(acc[r] + bv);
    }
}

// ---------------- A prep: f32 -> bf16 hi/lo split ----------------
__global__ void convert_split(const float* __restrict__ src) {
    size_t i = (size_t)blockIdx.x * blockDim.x + threadIdx.x;
    const size_t n = (size_t)N_GRAPHS * KDIM;
    if (i >= n) return;
    float v = src[i];
    bf16 h = __float2bfloat16(v);
    g_Ah[i] = h;
    g_Al[i] = __float2bfloat16(v - __bfloat162float(h));
}

// ---------------- B prep: transpose + bf16 split ----------------
__global__ void transB(const float* __restrict__ W) {
    __shared__ float t[32][33];
    int n0 = blockIdx.x * 32, k0 = blockIdx.y * 32;
    int tx = threadIdx.x, ty = threadIdx.y;
#pragma unroll
    for (int j = 0; j < 32; j += 8)
        t[ty + j][tx] = W[(size_t)(k0 + ty + j) * NDIM + n0 + tx];
    __syncthreads();
#pragma unroll
    for (int j = 0; j < 32; j += 8) {
        float v = t[tx][ty + j];
        bf16 h = __float2bfloat16(v);
        size_t oi = (size_t)(n0 + ty + j) * KDIM + k0 + tx;
        g_Bh[oi] = h;
        g_Bl[oi] = __float2bfloat16(v - __bfloat162float(h));
    }
}

// ---------------- tensor-core GEMM (mma.sync bf16): C = A @ B^T + bias ----
// 3-term split: Ah*Bh + Ah*Bl + Al*Bh, fp32 register accumulators.
// CTA 128x128, 8 warps (2x4), warp tile 64x32. K-stage 32, single smem
// buffer (static 40960B), next stage prefetched into registers before the
// MMA block so LDG latency overlaps tensor math.
#define TG_KB     32
#define TG_NSTG   (KDIM / TG_KB)       // 232
#define TG_RSTR   80                   // 64B data + 16B pad (16B-aligned rows)
#define TG_TILE   (128 * TG_RSTR)      // 10240
#define TG_SMEMB  (4 * TG_TILE)        // 40960

__global__ void __launch_bounds__(256)
tgemm(const float* __restrict__ bias, float* __restrict__ C) {
    __shared__ __align__(16) char smem[TG_SMEMB];
    const uint32_t sb = smem_u32(smem);
    const int tid = threadIdx.x;
    const int lane = tid & 31, wid = tid >> 5;
    const int wm = wid >> 2, wn = wid & 3;       // 2 x 4 warp grid
    const int brow = blockIdx.y * 128;
    const int bcol = blockIdx.x * 128;
    const int lr = lane & 15, hi = lane >> 4;

    // per-thread load geometry: each tile = 512 16B-chunks, 2 per thread.
    int row0c = (2 * tid) >> 2, c160 = (2 * tid) & 3;
    int row1c = (2 * tid + 1) >> 2, c161 = (2 * tid + 1) & 3;
    const bf16* srcs[4] = {
        g_Ah + (size_t)(brow + row0c) * KDIM + c160 * 8,
        g_Al + (size_t)(brow + row0c) * KDIM + c160 * 8,
        g_Bh + (size_t)(bcol + row0c) * KDIM + c160 * 8,
        g_Bl + (size_t)(bcol + row0c) * KDIM + c160 * 8 };
    const bf16* srcs1[4] = {
        g_Ah + (size_t)(brow + row1c) * KDIM + c161 * 8,
        g_Al + (size_t)(brow + row1c) * KDIM + c161 * 8,
        g_Bh + (size_t)(bcol + row1c) * KDIM + c161 * 8,
        g_Bl + (size_t)(bcol + row1c) * KDIM + c161 * 8 };
    uint32_t doff0 = row0c * TG_RSTR + c160 * 16;
    uint32_t doff1 = row1c * TG_RSTR + c161 * 16;

    float acc[16][4];
#pragma unroll
    for (int i = 0; i < 16; i++)
#pragma unroll
        for (int j = 0; j < 4; j++) acc[i][j] = 0.f;

    const uint32_t aoff = sb + (wm * 64 + lr) * TG_RSTR + hi * 16;
    const uint32_t boff = sb + 2 * TG_TILE + (wn * 32 + lr) * TG_RSTR + hi * 16;

    uint4 pf[8];
#pragma unroll
    for (int t = 0; t < 4; t++) {
        pf[2 * t]     = *(const uint4*)(srcs[t]);
        pf[2 * t + 1] = *(const uint4*)(srcs1[t]);
    }

    for (int s = 0; s < TG_NSTG; s++) {
        __syncthreads();   // previous compute done; smem free
#pragma unroll
        for (int t = 0; t < 4; t++) {
            *(uint4*)(smem + doff0 + t * TG_TILE) = pf[2 * t];
            *(uint4*)(smem + doff1 + t * TG_TILE) = pf[2 * t + 1];
        }
        __syncthreads();
        if (s + 1 < TG_NSTG) {
            int k0 = (s + 1) * TG_KB;
#pragma unroll
            for (int t = 0; t < 4; t++) {
                pf[2 * t]     = *(const uint4*)(srcs[t] + k0);
                pf[2 * t + 1] = *(const uint4*)(srcs1[t] + k0);
            }
        }
#pragma unroll
        for (int q = 0; q < 2; q++) {          // two k16 slices per stage
            uint32_t ah[16], al[16], bh[8], bl[8];
#pragma unroll
            for (int t = 0; t < 4; t++) {
                uint32_t ad = aoff + t * 16 * TG_RSTR + q * 32;
                LDSM4(&ah[4 * t], ad);
                LDSM4(&al[4 * t], ad + TG_TILE);
            }
#pragma unroll
            for (int u = 0; u < 2; u++) {
                uint32_t bd = boff + u * 16 * TG_RSTR + q * 32;
                LDSM4(&bh[4 * u], bd);
                LDSM4(&bl[4 * u], bd + TG_TILE);
            }
#pragma unroll
            for (int tm = 0; tm < 4; tm++) {
#pragma unroll
                for (int tn = 0; tn < 4; tn++) {
                    int u = tn >> 1, ss = tn & 1;
                    uint32_t bh0 = bh[4 * u + ss], bh1 = bh[4 * u + 2 + ss];
                    uint32_t bl0 = bl[4 * u + ss], bl1 = bl[4 * u + 2 + ss];
                    float* d = acc[tm * 4 + tn];
                    MMA_BF16(d, &ah[4 * tm], bh0, bh1);   // Ah*Bh
                    MMA_BF16(d, &ah[4 * tm], bl0, bl1);   // Ah*Bl
                    MMA_BF16(d, &al[4 * tm], bh0, bh1);   // Al*Bh
                }
            }
        }
    }

    // epilogue: d0:(r,c) d1:(r,c+1) d2:(r+8,c) d3:(r+8,c+1)
    const int orow = brow + wm * 64 + (lane >> 2);
    const int ocol = bcol + wn * 32 + (lane & 3) * 2;
#pragma unroll
    for (int tm = 0; tm < 4; tm++) {
#pragma unroll
        for (int tn = 0; tn < 4; tn++) {
            float* d = acc[tm * 4 + tn];
            int r = orow + tm * 16;
            int c = ocol + tn * 8;
            float b0 = bias[c], b1 = bias[c + 1];
            *(float2*)&C[(size_t)r * NDIM + c] = make_float2(d[0] + b0, d[1] + b1);
            *(float2*)&C[(size_t)(r + 8) * NDIM + c] = make_float2(d[2] + b0, d[3] + b1);
        }
    }
}

// ---------------- fused LayerNorm + mish + lin2 ----------------
__device__ __forceinline__ void block_reduce2(float& a, float& b, float* sbuf) {
#pragma unroll
    for (int o = 16; o; o >>= 1) {
        a += __shfl_down_sync(0xffffffffu, a, o);
        b += __shfl_down_sync(0xffffffffu, b, o);
    }
    int w = threadIdx.x >> 5;
    __syncthreads();
    if ((threadIdx.x & 31) == 0) { sbuf[w] = a; sbuf[w + 8] = b; }
    __syncthreads();
    if (threadIdx.x < 32) {
        a = (threadIdx.x < 8) ? sbuf[threadIdx.x] : 0.f;
        b = (threadIdx.x < 8) ? sbuf[threadIdx.x + 8] : 0.f;
#pragma unroll
        for (int o = 4; o; o >>= 1) {
            a += __shfl_down_sync(0xffffffffu, a, o);
            b += __shfl_down_sync(0xffffffffu, b, o);
        }
        if (threadIdx.x == 0) { sbuf[16] = a; sbuf[17] = b; }
    }
    __syncthreads();
    a = sbuf[16];
    b = sbuf[17];
}

__global__ void ln_mish_lin2(const float* __restrict__ H,
                             const float* __restrict__ g,
                             const float* __restrict__ bb,
                             const float* __restrict__ w2,
                             const float* __restrict__ b2,
                             float* __restrict__ out) {
    __shared__ float sbuf[18];
    int row = blockIdx.x;
    const float* h = H + (size_t)row * D1;
    int tid = threadIdx.x;

    float s = 0.f, s2 = 0.f;
    for (int k = tid; k < D1; k += 256) {
        float v = h[k];
        s += v;
        s2 = fmaf(v, v, s2);
    }
    block_reduce2(s, s2, sbuf);
    float mu = s * (1.0f / D1);
    float var = s2 * (1.0f / D1) - mu * mu;
    float rstd = rsqrtf(var + 1e-5f);

    float a0 = 0.f, a1 = 0.f;
    for (int k = tid; k < D1; k += 256) {
        float v = (h[k] - mu) * rstd * g[k] + bb[k];
        v = mish_f(v);
        a0 = fmaf(v, w2[2 * k + 0], a0);
        a1 = fmaf(v, w2[2 * k + 1], a1);
    }
    block_reduce2(a0, a1, sbuf);
    if (tid == 0) {
        out[2 * row + 0] = a0 + b2[0];
        out[2 * row + 1] = a1 + b2[1];
    }
}

// ---------------- launch ----------------
extern "C" void kernel_launch(void* const* d_in, const int* in_sizes, int n_in,
                              void* d_out, int out_size) {
    const float* x      = (const float*)d_in[0];
    const int*   ei     = (const int*)d_in[1];        // int32 (downcast from int64)
    const float* w1_l   = (const float*)d_in[2];
    const float* b1_l   = (const float*)d_in[3];
    const float* w1_r   = (const float*)d_in[4];
    const float* w2_l   = (const float*)d_in[5];
    const float* b2_l   = (const float*)d_in[6];
    const float* w2_r   = (const float*)d_in[7];
    const float* w_lin1 = (const float*)d_in[8];
    const float* b_lin1 = (const float*)d_in[9];
    const float* ln_g   = (const float*)d_in[10];
    const float* ln_b   = (const float*)d_in[11];
    const float* w_lin2 = (const float*)d_in[12];
    const float* b_lin2 = (const float*)d_in[13];
    float* out = (float*)d_out;

    const int E = in_sizes[1] / 2;
    const long long scatter_threads = (long long)E * 32;
    const int scatter_blocks = (int)((scatter_threads + 255) / 256);

    float* h1f = (float*)g_h1;
    float* h2f = (float*)g_h2;

    // ---- layer 1 (R2-proven) ----
    zero_agg_deg<<<4096, 256>>>();
    scatter_kernel<true><<<scatter_blocks, 256>>>((const float4*)x, ei, E);
    sage_gemm<N_ROI, 2><<<N_NODES / 32, dim3(N_ROI, 2)>>>(
        x, w1_l, w1_r, b1_l, h1f);

    // ---- layer 2 (R2-proven) ----
    zero_agg<<<4096, 256>>>();
    scatter_kernel<false><<<scatter_blocks, 256>>>((const float4*)g_h1, ei, E);
    sage_gemm<HIDDEN, 4><<<N_NODES / 32, dim3(HIDDEN, 4)>>>(
        h1f, w2_l, w2_r, b2_l, h2f);

    // ---- dense head (new path, isolated) ----
    const size_t nA = (size_t)N_GRAPHS * KDIM;
    convert_split<<<(int)((nA + 255) / 256), 256>>>(h2f);
    transB<<<dim3(NDIM / 32, KDIM / 32), dim3(32, 8)>>>(w_lin1);
    tgemm<<<dim3(NDIM / 128, N_GRAPHS / 128), 256>>>(b_lin1, g_lin1);
    ln_mish_lin2<<<N_GRAPHS, 256>>>(g_lin1, ln_g, ln_b, w_lin2, b_lin2, out);
}

// round 11
// speedup vs baseline: 1.6127x; 1.0214x over previous
#include <cuda_runtime.h>
#include <cuda_bf16.h>
#include <cstdint>

// ---------------- problem constants ----------------
#define N_ROI    116
#define HIDDEN   64
#define N_NODES  118784           // 1024 * 116 = 464 * 256
#define N_GRAPHS 1024
#define D1       3712             // 116*32
#define KDIM     7424             // 116*64
#define NDIM     3712
#define CH4      29               // 116 floats = 29 float4
#define E_MAX    1900544
#define NB_SCAN  (N_NODES / 256)  // 464

using bf16 = __nv_bfloat16;

// ---------------- scratch (no allocations allowed) ----------------
// NOTE: no buffer is ever accumulated into across kernels; gathers and
// GEMMs fully overwrite their outputs -> replay-safe with zero zero-kernels.
__device__ __align__(256) float4 g_agg[(size_t)N_NODES * CH4];    // 55.1 MB (gather sums; reused both layers)
__device__ __align__(256) float  g_deg[N_NODES];
__device__ __align__(256) float4 g_h1[(size_t)N_NODES * CH4];     // 55.1 MB
__device__ __align__(256) float4 g_h2[(size_t)N_NODES * (HIDDEN/4)]; // 30.4 MB
__device__ __align__(256) bf16   g_Ah[(size_t)N_GRAPHS * KDIM];   // 14.8 MB
__device__ __align__(256) bf16   g_Al[(size_t)N_GRAPHS * KDIM];   // 14.8 MB
__device__ __align__(256) bf16   g_Bh[(size_t)NDIM * KDIM];       // 55.1 MB
__device__ __align__(256) bf16   g_Bl[(size_t)NDIM * KDIM];       // 55.1 MB
__device__ __align__(256) float  g_lin1[(size_t)N_GRAPHS * D1];   // 15.2 MB
// CSR machinery (rebuilt from scratch every call)
__device__ int g_cnt[N_NODES];
__device__ int g_off[N_NODES + 1];
__device__ int g_cur[N_NODES];
__device__ int g_csrc[E_MAX];
__device__ int g_bsum[NB_SCAN];
__device__ int g_bbase[NB_SCAN];

// ---------------- inline PTX helpers ----------------
__device__ __forceinline__ uint32_t smem_u32(const void* p) {
    uint32_t a;
    asm("{ .reg .u64 t; cvta.to.shared.u64 t, %1; cvt.u32.u64 %0, t; }" : "=r"(a) : "l"(p));
    return a;
}
#define LDSM4(r, addr) \
    asm volatile("ldmatrix.sync.aligned.m8n8.x4.shared.b16 {%0,%1,%2,%3}, [%4];" \
        : "=r"((r)[0]), "=r"((r)[1]), "=r"((r)[2]), "=r"((r)[3]) : "r"(addr))
#define MMA_BF16(d, a, b0, b1) \
    asm volatile("mma.sync.aligned.m16n8k16.row.col.f32.bf16.bf16.f32 " \
        "{%0,%1,%2,%3}, {%4,%5,%6,%7}, {%8,%9}, {%0,%1,%2,%3};" \
        : "+f"((d)[0]), "+f"((d)[1]), "+f"((d)[2]), "+f"((d)[3]) \
        : "r"((a)[0]), "r"((a)[1]), "r"((a)[2]), "r"((a)[3]), "r"(b0), "r"(b1))

__device__ __forceinline__ float mish_f(float x) {
    float sp = (x > 20.0f) ? x : log1pf(__expf(x));
    return x * tanhf(sp);
}

// ================= CSR build (by dst) =================
__global__ void zero_cnt() {
    int i = blockIdx.x * blockDim.x + threadIdx.x;
    if (i < N_NODES) g_cnt[i] = 0;
}
__global__ void hist_kernel(const int* __restrict__ ei, int E) {
    for (int i = blockIdx.x * blockDim.x + threadIdx.x; i < E;
         i += gridDim.x * blockDim.x)
        atomicAdd(&g_cnt[ei[E + i]], 1);
}
__global__ void scan_part() {
    __shared__ int s[256];
    int t = threadIdx.x;
    s[t] = g_cnt[blockIdx.x * 256 + t];
    __syncthreads();
    for (int o = 128; o; o >>= 1) {
        if (t < o) s[t] += s[t + o];
        __syncthreads();
    }
    if (t == 0) g_bsum[blockIdx.x] = s[0];
}
__global__ void scan_top() {
    __shared__ int s[512];
    int t = threadIdx.x;
    int v = (t < NB_SCAN) ? g_bsum[t] : 0;
    s[t] = v;
    __syncthreads();
    for (int o = 1; o < 512; o <<= 1) {
        int x = (t >= o) ? s[t - o] : 0;
        __syncthreads();
        s[t] += x;
        __syncthreads();
    }
    if (t < NB_SCAN) g_bbase[t] = s[t] - v;   // exclusive
}
__global__ void scan_final() {
    __shared__ int s[256];
    int t = threadIdx.x;
    int i = blockIdx.x * 256 + t;
    int v = g_cnt[i];
    s[t] = v;
    __syncthreads();
    for (int o = 1; o < 256; o <<= 1) {
        int x = (t >= o) ? s[t - o] : 0;
        __syncthreads();
        s[t] += x;
        __syncthreads();
    }
    int incl = s[t];
    int base = g_bbase[blockIdx.x];
    int offv = base + incl - v;
    g_off[i] = offv;
    g_cur[i] = offv;
    if (i == N_NODES - 1) g_off[N_NODES] = base + incl;
}
__global__ void permute_kernel(const int* __restrict__ ei, int E) {
    for (int i = blockIdx.x * blockDim.x + threadIdx.x; i < E;
         i += gridDim.x * blockDim.x) {
        int d = ei[E + i];
        int pos = atomicAdd(&g_cur[d], 1);
        g_csrc[pos] = ei[i];
    }
}

// ============ gather: SUM of neighbor rows into g_agg, deg into g_deg ====
// warp per node; lanes 0..28 accumulate float4 chunks; lane 29 writes deg.
// OVERWRITES output -> no zeroing needed, reusable for both layers.
__global__ void gather_sum116(const float4* __restrict__ feat) {
    int warp = (blockIdx.x * blockDim.x + threadIdx.x) >> 5;
    int lane = threadIdx.x & 31;
    if (warp >= N_NODES) return;
    int beg = g_off[warp], end = g_off[warp + 1];
    if (lane == 29) { g_deg[warp] = (float)(end - beg); return; }
    if (lane >= CH4) return;
    float4 a0 = make_float4(0.f, 0.f, 0.f, 0.f);
    float4 a1 = make_float4(0.f, 0.f, 0.f, 0.f);
    int j = beg;
    for (; j + 1 < end; j += 2) {
        int s0 = g_csrc[j], s1 = g_csrc[j + 1];
        float4 v0 = feat[(size_t)s0 * CH4 + lane];
        float4 v1 = feat[(size_t)s1 * CH4 + lane];
        a0.x += v0.x; a0.y += v0.y; a0.z += v0.z; a0.w += v0.w;
        a1.x += v1.x; a1.y += v1.y; a1.z += v1.z; a1.w += v1.w;
    }
    if (j < end) {
        int s = g_csrc[j];
        float4 v = feat[(size_t)s * CH4 + lane];
        a0.x += v.x; a0.y += v.y; a0.z += v.z; a0.w += v.w;
    }
    float4 r;
    r.x = a0.x + a1.x; r.y = a0.y + a1.y;
    r.z = a0.z + a1.z; r.w = a0.w + a1.w;
    g_agg[(size_t)warp * CH4 + lane] = r;
}

// ---------------- fused SAGE layer GEMM (verbatim R7, proven) -------------
template<int NOUT, int NTY>
__global__ void sage_gemm(const float* __restrict__ A,
                          const float* __restrict__ WL,
                          const float* __restrict__ WR,
                          const float* __restrict__ bias,
                          float* __restrict__ out) {
    const int ROWS = 32, KC = 29, RPT = ROWS / NTY;
    __shared__ float as_[ROWS][KC];
    __shared__ float ms_[ROWS][KC];
    __shared__ float wl_[KC][NOUT];
    __shared__ float wr_[KC][NOUT];
    __shared__ float rdeg[ROWS];

    int tx = threadIdx.x, ty = threadIdx.y;
    int tid = ty * NOUT + tx;
    const int nthr = NOUT * NTY;
    int row0 = blockIdx.x * ROWS;
    const float* AGG = (const float*)g_agg;

    for (int i = tid; i < ROWS; i += nthr)
        rdeg[i] = 1.0f / fmaxf(g_deg[row0 + i], 1.0f);

    float acc[RPT];
#pragma unroll
    for (int r = 0; r < RPT; r++) acc[r] = 0.f;

    for (int kc = 0; kc < N_ROI; kc += KC) {
        __syncthreads();
        for (int i = tid; i < ROWS * KC; i += nthr) {
            int r = i / KC, k = i % KC;
            size_t gi = (size_t)(row0 + r) * N_ROI + kc + k;
            as_[r][k] = A[gi];
            ms_[r][k] = AGG[gi] * rdeg[r];
        }
        for (int i = tid; i < KC * NOUT; i += nthr) {
            int k = i / NOUT, j = i % NOUT;
            wl_[k][j] = WL[(size_t)(kc + k) * NOUT + j];
            wr_[k][j] = WR[(size_t)(kc + k) * NOUT + j];
        }
        __syncthreads();
#pragma unroll
        for (int k = 0; k < KC; k++) {
            float wlv = wl_[k][tx];
            float wrv = wr_[k][tx];
#pragma unroll
            for (int r = 0; r < RPT; r++) {
                int rr = r * NTY + ty;
                acc[r] = fmaf(ms_[rr][k], wlv, acc[r]);
                acc[r] = fmaf(as_[rr][k], wrv, acc[r]);
            }
        }
    }
    float bv = bias[tx];
#pragma unroll
    for (int r = 0; r < RPT; r++) {
        int rr = r * NTY + ty;
        out[(size_t)(row0 + rr) * NOUT + tx] = mish_f(acc[r] + bv);
    }
}

// ---------------- A prep: f32 -> bf16 hi/lo split (verbatim R7) -----------
__global__ void convert_split(const float* __restrict__ src) {
    size_t i = (size_t)blockIdx.x * blockDim.x + threadIdx.x;
    const size_t n = (size_t)N_GRAPHS * KDIM;
    if (i >= n) return;
    float v = src[i];
    bf16 h = __float2bfloat16(v);
    g_Ah[i] = h;
    g_Al[i] = __float2bfloat16(v - __bfloat162float(h));
}

// ---------------- B prep: transpose + bf16 split (verbatim R7) ------------
__global__ void transB(const float* __restrict__ W) {
    __shared__ float t[32][33];
    int n0 = blockIdx.x * 32, k0 = blockIdx.y * 32;
    int tx = threadIdx.x, ty = threadIdx.y;
#pragma unroll
    for (int j = 0; j < 32; j += 8)
        t[ty + j][tx] = W[(size_t)(k0 + ty + j) * NDIM + n0 + tx];
    __syncthreads();
#pragma unroll
    for (int j = 0; j < 32; j += 8) {
        float v = t[tx][ty + j];
        bf16 h = __float2bfloat16(v);
        size_t oi = (size_t)(n0 + ty + j) * KDIM + k0 + tx;
        g_Bh[oi] = h;
        g_Bl[oi] = __float2bfloat16(v - __bfloat162float(h));
    }
}

// ---------------- tensor-core GEMM (verbatim R7, proven) ------------------
#define TG_KB     32
#define TG_NSTG   (KDIM / TG_KB)       // 232
#define TG_RSTR   80
#define TG_TILE   (128 * TG_RSTR)      // 10240
#define TG_SMEMB  (4 * TG_TILE)        // 40960

__global__ void __launch_bounds__(256)
tgemm(const float* __restrict__ bias, float* __restrict__ C) {
    __shared__ __align__(16) char smem[TG_SMEMB];
    const uint32_t sb = smem_u32(smem);
    const int tid = threadIdx.x;
    const int lane = tid & 31, wid = tid >> 5;
    const int wm = wid >> 2, wn = wid & 3;
    const int brow = blockIdx.y * 128;
    const int bcol = blockIdx.x * 128;
    const int lr = lane & 15, hi = lane >> 4;

    int row0c = (2 * tid) >> 2, c160 = (2 * tid) & 3;
    int row1c = (2 * tid + 1) >> 2, c161 = (2 * tid + 1) & 3;
    const bf16* srcs[4] = {
        g_Ah + (size_t)(brow + row0c) * KDIM + c160 * 8,
        g_Al + (size_t)(brow + row0c) * KDIM + c160 * 8,
        g_Bh + (size_t)(bcol + row0c) * KDIM + c160 * 8,
        g_Bl + (size_t)(bcol + row0c) * KDIM + c160 * 8 };
    const bf16* srcs1[4] = {
        g_Ah + (size_t)(brow + row1c) * KDIM + c161 * 8,
        g_Al + (size_t)(brow + row1c) * KDIM + c161 * 8,
        g_Bh + (size_t)(bcol + row1c) * KDIM + c161 * 8,
        g_Bl + (size_t)(bcol + row1c) * KDIM + c161 * 8 };
    uint32_t doff0 = row0c * TG_RSTR + c160 * 16;
    uint32_t doff1 = row1c * TG_RSTR + c161 * 16;

    float acc[16][4];
#pragma unroll
    for (int i = 0; i < 16; i++)
#pragma unroll
        for (int j = 0; j < 4; j++) acc[i][j] = 0.f;

    const uint32_t aoff = sb + (wm * 64 + lr) * TG_RSTR + hi * 16;
    const uint32_t boff = sb + 2 * TG_TILE + (wn * 32 + lr) * TG_RSTR + hi * 16;

    uint4 pf[8];
#pragma unroll
    for (int t = 0; t < 4; t++) {
        pf[2 * t]     = *(const uint4*)(srcs[t]);
        pf[2 * t + 1] = *(const uint4*)(srcs1[t]);
    }

    for (int s = 0; s < TG_NSTG; s++) {
        __syncthreads();
#pragma unroll
        for (int t = 0; t < 4; t++) {
            *(uint4*)(smem + doff0 + t * TG_TILE) = pf[2 * t];
            *(uint4*)(smem + doff1 + t * TG_TILE) = pf[2 * t + 1];
        }
        __syncthreads();
        if (s + 1 < TG_NSTG) {
            int k0 = (s + 1) * TG_KB;
#pragma unroll
            for (int t = 0; t < 4; t++) {
                pf[2 * t]     = *(const uint4*)(srcs[t] + k0);
                pf[2 * t + 1] = *(const uint4*)(srcs1[t] + k0);
            }
        }
#pragma unroll
        for (int q = 0; q < 2; q++) {
            uint32_t ah[16], al[16], bh[8], bl[8];
#pragma unroll
            for (int t = 0; t < 4; t++) {
                uint32_t ad = aoff + t * 16 * TG_RSTR + q * 32;
                LDSM4(&ah[4 * t], ad);
                LDSM4(&al[4 * t], ad + TG_TILE);
            }
#pragma unroll
            for (int u = 0; u < 2; u++) {
                uint32_t bd = boff + u * 16 * TG_RSTR + q * 32;
                LDSM4(&bh[4 * u], bd);
                LDSM4(&bl[4 * u], bd + TG_TILE);
            }
#pragma unroll
            for (int tm = 0; tm < 4; tm++) {
#pragma unroll
                for (int tn = 0; tn < 4; tn++) {
                    int u = tn >> 1, ss = tn & 1;
                    uint32_t bh0 = bh[4 * u + ss], bh1 = bh[4 * u + 2 + ss];
                    uint32_t bl0 = bl[4 * u + ss], bl1 = bl[4 * u + 2 + ss];
                    float* d = acc[tm * 4 + tn];
                    MMA_BF16(d, &ah[4 * tm], bh0, bh1);
                    MMA_BF16(d, &ah[4 * tm], bl0, bl1);
                    MMA_BF16(d, &al[4 * tm], bh0, bh1);
                }
            }
        }
    }

    const int orow = brow + wm * 64 + (lane >> 2);
    const int ocol = bcol + wn * 32 + (lane & 3) * 2;
#pragma unroll
    for (int tm = 0; tm < 4; tm++) {
#pragma unroll
        for (int tn = 0; tn < 4; tn++) {
            float* d = acc[tm * 4 + tn];
            int r = orow + tm * 16;
            int c = ocol + tn * 8;
            float b0 = bias[c], b1 = bias[c + 1];
            *(float2*)&C[(size_t)r * NDIM + c] = make_float2(d[0] + b0, d[1] + b1);
            *(float2*)&C[(size_t)(r + 8) * NDIM + c] = make_float2(d[2] + b0, d[3] + b1);
        }
    }
}

// ---------------- fused LayerNorm + mish + lin2 (verbatim R7) -------------
__device__ __forceinline__ void block_reduce2(float& a, float& b, float* sbuf) {
#pragma unroll
    for (int o = 16; o; o >>= 1) {
        a += __shfl_down_sync(0xffffffffu, a, o);
        b += __shfl_down_sync(0xffffffffu, b, o);
    }
    int w = threadIdx.x >> 5;
    __syncthreads();
    if ((threadIdx.x & 31) == 0) { sbuf[w] = a; sbuf[w + 8] = b; }
    __syncthreads();
    if (threadIdx.x < 32) {
        a = (threadIdx.x < 8) ? sbuf[threadIdx.x] : 0.f;
        b = (threadIdx.x < 8) ? sbuf[threadIdx.x + 8] : 0.f;
#pragma unroll
        for (int o = 4; o; o >>= 1) {
            a += __shfl_down_sync(0xffffffffu, a, o);
            b += __shfl_down_sync(0xffffffffu, b, o);
        }
        if (threadIdx.x == 0) { sbuf[16] = a; sbuf[17] = b; }
    }
    __syncthreads();
    a = sbuf[16];
    b = sbuf[17];
}

__global__ void ln_mish_lin2(const float* __restrict__ H,
                             const float* __restrict__ g,
                             const float* __restrict__ bb,
                             const float* __restrict__ w2,
                             const float* __restrict__ b2,
                             float* __restrict__ out) {
    __shared__ float sbuf[18];
    int row = blockIdx.x;
    const float* h = H + (size_t)row * D1;
    int tid = threadIdx.x;

    float s = 0.f, s2 = 0.f;
    for (int k = tid; k < D1; k += 256) {
        float v = h[k];
        s += v;
        s2 = fmaf(v, v, s2);
    }
    block_reduce2(s, s2, sbuf);
    float mu = s * (1.0f / D1);
    float var = s2 * (1.0f / D1) - mu * mu;
    float rstd = rsqrtf(var + 1e-5f);

    float a0 = 0.f, a1 = 0.f;
    for (int k = tid; k < D1; k += 256) {
        float v = (h[k] - mu) * rstd * g[k] + bb[k];
        v = mish_f(v);
        a0 = fmaf(v, w2[2 * k + 0], a0);
        a1 = fmaf(v, w2[2 * k + 1], a1);
    }
    block_reduce2(a0, a1, sbuf);
    if (tid == 0) {
        out[2 * row + 0] = a0 + b2[0];
        out[2 * row + 1] = a1 + b2[1];
    }
}

// ---------------- launch ----------------
extern "C" void kernel_launch(void* const* d_in, const int* in_sizes, int n_in,
                              void* d_out, int out_size) {
    const float* x      = (const float*)d_in[0];
    const int*   ei     = (const int*)d_in[1];
    const float* w1_l   = (const float*)d_in[2];
    const float* b1_l   = (const float*)d_in[3];
    const float* w1_r   = (const float*)d_in[4];
    const float* w2_l   = (const float*)d_in[5];
    const float* b2_l   = (const float*)d_in[6];
    const float* w2_r   = (const float*)d_in[7];
    const float* w_lin1 = (const float*)d_in[8];
    const float* b_lin1 = (const float*)d_in[9];
    const float* ln_g   = (const float*)d_in[10];
    const float* ln_b   = (const float*)d_in[11];
    const float* w_lin2 = (const float*)d_in[12];
    const float* b_lin2 = (const float*)d_in[13];
    float* out = (float*)d_out;

    int E = in_sizes[1] / 2;
    if (E > E_MAX) E = E_MAX;

    float* h1f = (float*)g_h1;
    float* h2f = (float*)g_h2;
    const int GATHER_BLKS = (N_NODES * 32) / 256;

    // ---- CSR build (int atomics only) ----
    zero_cnt<<<(N_NODES + 511) / 512, 512>>>();                        // 0
    transB<<<dim3(NDIM / 32, KDIM / 32), dim3(32, 8)>>>(w_lin1);       // 1
    hist_kernel<<<1024, 256>>>(ei, E);                                 // 2
    scan_part<<<NB_SCAN, 256>>>();                                     // 3
    scan_top<<<1, 512>>>();                                            // 4
    scan_final<<<NB_SCAN, 256>>>();                                    // 5
    permute_kernel<<<1024, 256>>>(ei, E);                              // 6

    // ---- layer 1: gather sums(x) + deg -> g_agg/g_deg, fused SAGE GEMM ----
    gather_sum116<<<GATHER_BLKS, 256>>>((const float4*)x);             // 7
    sage_gemm<N_ROI, 2><<<N_NODES / 32, dim3(N_ROI, 2)>>>(             // 8
        x, w1_l, w1_r, b1_l, h1f);

    // ---- layer 2: gather sums(h1) OVERWRITES g_agg, fused SAGE GEMM ----
    gather_sum116<<<GATHER_BLKS, 256>>>((const float4*)g_h1);          // 9
    sage_gemm<HIDDEN, 4><<<N_NODES / 32, dim3(HIDDEN, 4)>>>(           // 10
        h1f, w2_l, w2_r, b2_l, h2f);

    // ---- dense head (verbatim R7) ----
    const size_t nA = (size_t)N_GRAPHS * KDIM;
    convert_split<<<(int)((nA + 255) / 256), 256>>>(h2f);              // 11
    tgemm<<<dim3(NDIM / 128, N_GRAPHS / 128), 256>>>(b_lin1, g_lin1);  // 12
    ln_mish_lin2<<<N_GRAPHS, 256>>>(g_lin1, ln_g, ln_b, w_lin2, b_lin2, out); // 13
}